// round 16
// baseline (speedup 1.0000x reference)
#include <cuda_runtime.h>
#include <cuda_bf16.h>
#include <cuda_fp16.h>
#include <math_constants.h>

#define T_TOK 8192
#define DIM   256
#define NSLOT 4096
#define FULLM 0xffffffffu
typedef unsigned int u32;
typedef unsigned long long u64;
typedef __nv_bfloat16 bf16;

// ---------------- scratch ----------------
__device__ float g_k[T_TOK * DIM];
__device__ float g_v[T_TOK * DIM];
__device__ u64   g_cmax[T_TOK];
__device__ u64   g_cmax2[T_TOK];
__device__ unsigned g_info[T_TOK];
__device__ unsigned g_pick[T_TOK];
__device__ float g_act[NSLOT];
__device__ float g_lb[NSLOT];
__device__ float g_bias[3 * DIM];
__device__ float g_vb[NSLOT * DIM];
__device__ float g_rowsum[T_TOK];
__device__ int   g_scanflag;
__device__ int   g_simflag;
__device__ float g_part[2 * T_TOK * DIM];

__device__ __half g_xh[T_TOK*DIM];
__device__ bf16 g_khi[T_TOK*DIM], g_klo[T_TOK*DIM];
__device__ __half g_qh[T_TOK*DIM];
__device__ __half g_wk16h[DIM*DIM], g_wk16l[DIM*DIM];
__device__ __half g_wv16h[DIM*DIM], g_wv16l[DIM*DIM];
__device__ __half g_wq16h[DIM*DIM], g_wq16l[DIM*DIM];
__device__ bf16 g_k0h[NSLOT*DIM], g_k0l[NSLOT*DIM];
__device__ __half g_kbh[NSLOT*DIM], g_kbl[NSLOT*DIM];
__device__ __half g_vth[DIM*NSLOT];
__device__ __half g_Eh[(size_t)T_TOK*NSLOT];

// ---------------- helpers ----------------
__device__ __forceinline__ u32 cvta_sm(const void* p){
    u32 a; asm("{.reg .u64 t; cvta.to.shared.u64 t, %1; cvt.u32.u64 %0, t;}" : "=r"(a) : "l"(p));
    return a;
}
__device__ __forceinline__ u32 fmap(float f){
    u32 b = __float_as_uint(f);
    return (b & 0x80000000u) ? ~b : (b | 0x80000000u);
}
__device__ __forceinline__ float funmap(u32 u){
    u32 b = (u & 0x80000000u) ? (u ^ 0x80000000u) : ~u;
    return __uint_as_float(b);
}
#define CPA(dst, src) asm volatile("cp.async.cg.shared.global [%0], [%1], 16;" :: "r"(dst), "l"(src))
#define CPCOMMIT()    asm volatile("cp.async.commit_group;" ::: "memory")
#define CPWAIT1()     asm volatile("cp.async.wait_group 1;" ::: "memory")
#define CPWAIT0()     asm volatile("cp.async.wait_group 0;" ::: "memory")
#define LDX4(r, a) asm volatile("ldmatrix.sync.aligned.m8n8.x4.shared.b16 {%0,%1,%2,%3}, [%4];" \
    : "=r"((r)[0]), "=r"((r)[1]), "=r"((r)[2]), "=r"((r)[3]) : "r"(a))
#define MMAB(D, A, B0, B1) asm volatile( \
    "mma.sync.aligned.m16n8k16.row.col.f32.bf16.bf16.f32 " \
    "{%0,%1,%2,%3}, {%4,%5,%6,%7}, {%8,%9}, {%0,%1,%2,%3};" \
    : "+f"((D)[0]), "+f"((D)[1]), "+f"((D)[2]), "+f"((D)[3]) \
    : "r"((A)[0]), "r"((A)[1]), "r"((A)[2]), "r"((A)[3]), "r"(B0), "r"(B1))
#define MMAH(D, A, B0, B1) asm volatile( \
    "mma.sync.aligned.m16n8k16.row.col.f32.f16.f16.f32 " \
    "{%0,%1,%2,%3}, {%4,%5,%6,%7}, {%8,%9}, {%0,%1,%2,%3};" \
    : "+f"((D)[0]), "+f"((D)[1]), "+f"((D)[2]), "+f"((D)[3]) \
    : "r"((A)[0]), "r"((A)[1]), "r"((A)[2]), "r"((A)[3]), "r"(B0), "r"(B1))

#define PITCH 80
#define ABUF  10240
#define BUFSZ 40960
#define SMEMSZ 81920
#define SHIFTC 1.0f

// ---------------- universal mma.sync GEMM ----------------
// TERMS=3 bf16 (simmax-exact), TERMS=1 bf16 (simmax+guard),
// TERMS=2 fp16 (proj: A=xh, B=W h+l), TERMS=1 fp16 (attnA/attnC)
// mode: 0 proj (z+zofs = k/v/q), 3 simmax, 4 attnA, 5 attnC splitK, 6 simmax exact
template<int TERMS, bool H>
__global__ __launch_bounds__(256, 2) void mm_gemm(int mode, int zofs)
{
    if (mode == 6 && g_simflag == 0) return;
    const bool guard = (mode == 3) && (TERMS == 1);
    if (mode == 6) mode = 3;

    extern __shared__ char smx[];
    u32 smb = cvta_sm(smx);
    int tid = threadIdx.x, lane = tid & 31, wid = tid >> 5;
    int wm = wid >> 2, wn = wid & 3;
    int m0 = blockIdx.x * 128, n0 = blockIdx.y * 128;
    int bz = blockIdx.z + zofs;

    const void *pAh, *pAl, *pBh, *pBl; size_t lda, ldb; int K;
    float* out = 0;
    switch (mode){
    case 0:
        pAh = g_xh; pAl = g_xh; lda = ldb = DIM; K = DIM;
        if (bz == 0){ pBh=g_wk16h; pBl=g_wk16l; out=g_k; }
        else if (bz == 1){ pBh=g_wv16h; pBl=g_wv16l; out=g_v; }
        else { pBh=g_wq16h; pBl=g_wq16l; }
        break;
    case 3: pAh=g_khi; pAl=g_klo; pBh=g_k0h; pBl=g_k0l; lda=ldb=DIM; K=DIM; break;
    case 4: pAh=g_qh;  pAl=g_qh;  pBh=g_kbh; pBl=g_kbl; lda=ldb=DIM; K=DIM; break;
    default: pAh=g_Eh; pAl=g_Eh; pBh=g_vth; pBl=g_vth; lda=ldb=NSLOT; K=NSLOT;
             out=g_part + (size_t)bz * T_TOK * DIM; break;
    }
    int Kper = (mode == 5) ? K / gridDim.z : K;
    size_t kbase = (mode == 5) ? (size_t)blockIdx.z * Kper * 2 : 0;
    const char* gsrc[4];
    gsrc[0] = (const char*)pAh + (size_t)m0*lda*2 + kbase;
    gsrc[1] = (const char*)pAl + (size_t)m0*lda*2 + kbase;
    gsrc[2] = (const char*)pBh + (size_t)n0*ldb*2 + kbase;
    gsrc[3] = (const char*)pBl + (size_t)n0*ldb*2 + kbase;
    size_t rstA = lda*2, rstB = ldb*2;

    int a_ro = (lane & 7) + ((lane & 8) ? 8 : 0);
    int a_ko = (lane & 16) ? 8 : 0;
    int b_ro = (lane & 7) + ((lane & 16) ? 8 : 0);
    int b_ko = (lane & 8) ? 8 : 0;

    float d[4][4][4] = {};
    int nk = Kper / 32;
    {
        int row = (tid >> 2), kc = tid & 3;
#pragma unroll
        for (int arr = 0; arr < 4; arr++){
            if ((TERMS == 1 && (arr & 1)) || (TERMS == 2 && arr == 1)) continue;
            size_t rs = (arr < 2) ? rstA : rstB;
            u32 db = smb + arr*ABUF;
            CPA(db + (u32)row*PITCH + kc*16, gsrc[arr] + (size_t)row*rs + kc*16);
            CPA(db + (u32)(row+64)*PITCH + kc*16, gsrc[arr] + (size_t)(row+64)*rs + kc*16);
        }
        CPCOMMIT();
    }

    for (int ck = 0; ck < nk; ck++){
        if (ck + 1 < nk){
            int row = (tid >> 2), kc = tid & 3;
            size_t koff = (size_t)(ck + 1) * 64;
            u32 db = smb + ((ck + 1) & 1) * BUFSZ;
#pragma unroll
            for (int arr = 0; arr < 4; arr++){
                if ((TERMS == 1 && (arr & 1)) || (TERMS == 2 && arr == 1)) continue;
                size_t rs = (arr < 2) ? rstA : rstB;
                const char* s = gsrc[arr] + koff;
                CPA(db + arr*ABUF + (u32)row*PITCH + kc*16, s + (size_t)row*rs + kc*16);
                CPA(db + arr*ABUF + (u32)(row+64)*PITCH + kc*16, s + (size_t)(row+64)*rs + kc*16);
            }
            CPCOMMIT();
            CPWAIT1();
        } else {
            CPWAIT0();
        }
        __syncthreads();
        u32 bb = smb + (ck & 1) * BUFSZ;
#pragma unroll
        for (int ks = 0; ks < 2; ks++){
            u32 Abase = bb + (u32)(wm*64 + a_ro)*PITCH + (ks*16 + a_ko)*2;
            u32 Bbase = bb + 2*ABUF + (u32)(wn*32 + b_ro)*PITCH + (ks*16 + b_ko)*2;
            u32 bh[2][4], a[4][4];
            LDX4(bh[0], Bbase); LDX4(bh[1], Bbase + 16*PITCH);
#pragma unroll
            for (int ma = 0; ma < 4; ma++) LDX4(a[ma], Abase + ma*16*PITCH);
#pragma unroll
            for (int ma = 0; ma < 4; ma++)
#pragma unroll
                for (int na = 0; na < 4; na++){
                    if (H) MMAH(d[ma][na], a[ma], bh[na>>1][(na&1)*2], bh[na>>1][(na&1)*2+1]);
                    else   MMAB(d[ma][na], a[ma], bh[na>>1][(na&1)*2], bh[na>>1][(na&1)*2+1]);
                }
            if (TERMS >= 2){
                u32 blr[2][4];
                LDX4(blr[0], Bbase + ABUF); LDX4(blr[1], Bbase + ABUF + 16*PITCH);
#pragma unroll
                for (int ma = 0; ma < 4; ma++)
#pragma unroll
                    for (int na = 0; na < 4; na++){
                        if (H) MMAH(d[ma][na], a[ma], blr[na>>1][(na&1)*2], blr[na>>1][(na&1)*2+1]);
                        else   MMAB(d[ma][na], a[ma], blr[na>>1][(na&1)*2], blr[na>>1][(na&1)*2+1]);
                    }
            }
            if (TERMS == 3){
                u32 a2[4][4];
#pragma unroll
                for (int ma = 0; ma < 4; ma++) LDX4(a2[ma], Abase + ABUF + ma*16*PITCH);
#pragma unroll
                for (int ma = 0; ma < 4; ma++)
#pragma unroll
                    for (int na = 0; na < 4; na++)
                        MMAB(d[ma][na], a2[ma], bh[na>>1][(na&1)*2], bh[na>>1][(na&1)*2+1]);
            }
        }
        __syncthreads();
    }

    int qr = lane >> 2, qc = lane & 3;

    if (mode == 0){
        const float* bias = g_bias + bz * DIM;
#pragma unroll
        for (int ma = 0; ma < 4; ma++)
#pragma unroll
            for (int rs = 0; rs < 2; rs++){
                int row = m0 + wm*64 + ma*16 + rs*8 + qr;
#pragma unroll
                for (int na = 0; na < 4; na++){
                    int cg = n0 + wn*32 + na*8 + 2*qc;
                    float v0 = d[ma][na][rs*2]   + bias[cg];
                    float v1 = d[ma][na][rs*2+1] + bias[cg+1];
                    if (bz == 2){
                        *(__half2*)&g_qh[(size_t)row*DIM + cg] = __floats2half2_rn(v0, v1);
                    } else {
                        *(float2*)&out[(size_t)row*DIM + cg] = make_float2(v0, v1);
                        if (bz == 0){
                            bf16 h0 = __float2bfloat16(v0), h1 = __float2bfloat16(v1);
                            *(__nv_bfloat162*)&g_khi[(size_t)row*DIM+cg] = __nv_bfloat162(h0, h1);
                            *(__nv_bfloat162*)&g_klo[(size_t)row*DIM+cg] = __nv_bfloat162(
                                __float2bfloat16(v0 - __bfloat162float(h0)),
                                __float2bfloat16(v1 - __bfloat162float(h1)));
                        }
                    }
                }
            }
    } else if (mode == 3){
        u64* cm = guard ? g_cmax : g_cmax2;
#pragma unroll
        for (int ma = 0; ma < 4; ma++)
#pragma unroll
            for (int rs = 0; rs < 2; rs++){
                int row = m0 + wm*64 + ma*16 + rs*8 + qr;
                float bv = -CUDART_INF_F; int bi = 0x7fffffff;
#pragma unroll
                for (int na = 0; na < 4; na++)
#pragma unroll
                    for (int e = 0; e < 2; e++){
                        float v = d[ma][na][rs*2+e];
                        int col = n0 + wn*32 + na*8 + 2*qc + e;
                        if (v > bv){ bv = v; bi = col; }
                    }
#pragma unroll
                for (int o = 1; o < 4; o <<= 1){
                    float ov = __shfl_xor_sync(FULLM, bv, o);
                    int   oi = __shfl_xor_sync(FULLM, bi, o);
                    if (ov > bv || (ov == bv && oi < bi)){ bv = ov; bi = oi; }
                }
                if (qc == 0){
                    atomicMax(&cm[row], ((u64)fmap(bv) << 32) | (u32)(~(u32)bi));
                    if (guard && bv >= 7.4f) atomicOr(&g_simflag, 1);
                }
            }
    } else if (mode == 4){
#pragma unroll
        for (int ma = 0; ma < 4; ma++)
#pragma unroll
            for (int rs = 0; rs < 2; rs++){
                int row = m0 + wm*64 + ma*16 + rs*8 + qr;
                float rsum = 0.f;
#pragma unroll
                for (int na = 0; na < 4; na++){
                    int cg = n0 + wn*32 + na*8 + 2*qc;
                    float e0 = __expf(d[ma][na][rs*2]  *0.0625f + g_lb[cg]   - SHIFTC);
                    float e1 = __expf(d[ma][na][rs*2+1]*0.0625f + g_lb[cg+1] - SHIFTC);
                    rsum += e0 + e1;
                    *(__half2*)&g_Eh[(size_t)row*NSLOT + cg] = __floats2half2_rn(e0, e1);
                }
                rsum += __shfl_xor_sync(FULLM, rsum, 1);
                rsum += __shfl_xor_sync(FULLM, rsum, 2);
                if (qc == 0) atomicAdd(&g_rowsum[row], rsum);
            }
    } else {
#pragma unroll
        for (int ma = 0; ma < 4; ma++)
#pragma unroll
            for (int rs = 0; rs < 2; rs++){
                int row = m0 + wm*64 + ma*16 + rs*8 + qr;
#pragma unroll
                for (int na = 0; na < 4; na++){
                    int cg = n0 + wn*32 + na*8 + 2*qc;
                    *(float2*)&out[(size_t)row*DIM + cg] =
                        make_float2(d[ma][na][rs*2], d[ma][na][rs*2+1]);
                }
            }
    }
}

// ---------------- attnC reduce (2 partials) ----------------
__global__ void attnC_red(float* __restrict__ out)
{
    int i = blockIdx.x * blockDim.x + threadIdx.x;
    int row = i >> 6;
    float inv = 1.0f / g_rowsum[row];
    float4 s = *(float4*)&g_part[(size_t)i*4];
    float4 b = *(float4*)&g_part[(size_t)T_TOK*DIM + i*4];
    s.x = (s.x+b.x)*inv; s.y = (s.y+b.y)*inv;
    s.z = (s.z+b.z)*inv; s.w = (s.w+b.w)*inv;
    *(float4*)&out[(size_t)i*4] = s;
}

// ---------------- splits ----------------
__device__ __forceinline__ void split_bf(const float* src, bf16* h, bf16* l, int n, int tid, int nth)
{
    for (int i = tid; i < n; i += nth){
        float v = src[i];
        bf16 hi = __float2bfloat16(v);
        h[i] = hi;
        l[i] = __float2bfloat16(v - __bfloat162float(hi));
    }
}
__device__ __forceinline__ void split_h16(const float* src, __half* h, __half* l, int n, int tid, int nth)
{
    for (int i = tid; i < n; i += nth){
        float v = src[i];
        __half hi = __float2half_rn(v);
        h[i] = hi;
        l[i] = __float2half_rn(v - __half2float(hi));
    }
}
__global__ void splitAB_kernel(const float* __restrict__ x, const float* __restrict__ Wk,
                               const float* __restrict__ Wv, const float* __restrict__ Wq,
                               const float* __restrict__ keys0,
                               const float* __restrict__ bk, const float* __restrict__ bv,
                               const float* __restrict__ bq)
{
    int tid = blockIdx.x * blockDim.x + threadIdx.x;
    if (tid == 0) g_simflag = 0;
    int nth = gridDim.x * blockDim.x;
    if (tid < DIM){
        g_bias[tid] = bk[tid];
        g_bias[DIM + tid] = bv[tid];
        g_bias[2*DIM + tid] = bq[tid];
    }
    for (int t = tid; t < T_TOK; t += nth){ g_cmax[t] = 0ull; g_cmax2[t] = 0ull; }
    for (int i = tid; i < T_TOK*DIM; i += nth) g_xh[i] = __float2half_rn(x[i]);
    split_h16(Wk, g_wk16h, g_wk16l, DIM*DIM, tid, nth);
    split_h16(Wv, g_wv16h, g_wv16l, DIM*DIM, tid, nth);
    split_h16(Wq, g_wq16h, g_wq16l, DIM*DIM, tid, nth);
    split_bf(keys0, g_k0h, g_k0l, NSLOT*DIM, tid, nth);
}

// vb fp16 transpose (single)
__global__ void tsplit_vb()
{
    __shared__ float t[32][33];
    int x = threadIdx.x, y = threadIdx.y;
    int nb = blockIdx.x * 32, db = blockIdx.y * 32;
#pragma unroll
    for (int j = 0; j < 4; j++)
        t[y + 8*j][x] = g_vb[(size_t)(nb + y + 8*j)*DIM + db + x];
    __syncthreads();
#pragma unroll
    for (int j = 0; j < 4; j++){
        float v = t[x][y + 8*j];
        g_vth[(size_t)(db + y + 8*j)*NSLOT + nb + x] = __float2half_rn(v);
    }
}

// ---------------- parallel scan: trajectory sort ---------------------------
#define SP_SMEM (131072 + 32768 + 16384 + 64)
__global__ __launch_bounds__(1024) void scan_par(const float* __restrict__ act0,
                                                 const void* __restrict__ maskptr)
{
    extern __shared__ char sm[];
    u64* keys = (u64*)sm;
    u32* ml   = (u32*)(sm + 131072);
    int* cnt  = (int*)(sm + 131072 + 32768);
    int* ctl  = (int*)(sm + 131072 + 32768 + 16384);
    int tid = threadIdx.x;
    if (tid == 0){ ctl[0] = 0; }
    __syncthreads();

    const u64* cm = g_simflag ? g_cmax2 : g_cmax;
    const unsigned* w = (const unsigned*)maskptr;
    bool bytemode = (w[0] == 0x01010101u);

    u32 inf8[8]; int myc = 0;
    int base = tid * 8;
#pragma unroll
    for (int j = 0; j < 8; j++){
        int t = base + j;
        u64 c = cm[t];
        float best = funmap((u32)(c >> 32));
        int bi = (int)(~(u32)c) & 0xFFFF;
        bool novel = (best * 0.0625f) < 0.5f;
        bool m = bytemode ? (((const unsigned char*)maskptr)[t] != 0) : (w[t] != 0);
        u32 inf = (u32)bi | (novel ? 0x10000u : 0u) | (m ? 0x20000u : 0u);
        g_info[t] = inf;
        inf8[j] = inf;
        if ((inf & 0x30000u) == 0x20000u) atomicOr(&ctl[0], 1);
        if (inf & 0x20000u) myc++;
    }
    for (int s = tid; s < NSLOT; s += 1024){
        float a = act0[s];
        if (!(a >= 0.0f)) atomicOr(&ctl[0], 1);
    }
    cnt[tid] = myc;
    __syncthreads();
    for (int off = 1; off < 1024; off <<= 1){
        int v = (tid >= off) ? cnt[tid - off] : 0;
        __syncthreads();
        cnt[tid] += v;
        __syncthreads();
    }
    int mybase = cnt[tid] - myc;
    int m_count = cnt[1023];
    {
        int wr = mybase;
#pragma unroll
        for (int j = 0; j < 8; j++)
            if (inf8[j] & 0x20000u) ml[wr++] = base + j;
    }
    __syncthreads();

    u32 lov = 0, hiv = 0x3F7FFFFFu;
    for (int pass = 0; pass < 2 || lov < hiv; ){
        u32 mid = (pass < 2) ? hiv : lov + ((hiv - lov) >> 1);
        float V = __uint_as_float(mid);
        __syncthreads();
        if (tid == 0) ctl[1] = 0;
        __syncthreads();
        int c = 0;
        for (int s = tid; s < NSLOT; s += 1024){
            float v = act0[s]; int g = 0;
            while (v < 1.0f && v <= V && g < 64){ c++; g++; v = fminf(1.0f, v + 0.1f); }
        }
#pragma unroll
        for (int o = 16; o; o >>= 1) c += __shfl_xor_sync(FULLM, c, o);
        if ((tid & 31) == 0) atomicAdd(&ctl[1], c);
        __syncthreads();
        int tot = ctl[1];
        if (pass < 2){
            if (pass == 0 && tot < m_count){ if (tid == 0) ctl[0] = 1; }
            pass = 2;
            if (ctl[0]) break;
            if (tot >= m_count) ; else lov = hiv;
        } else {
            if (tot >= m_count) hiv = mid; else lov = mid + 1;
        }
    }
    __syncthreads();
    if (ctl[0]){ if (tid == 0) g_scanflag = 1; return; }
    if (tid == 0) g_scanflag = 0;
    float Vf = __uint_as_float(hiv);

    if (tid == 0) ctl[2] = 0;
    for (int i = tid; i < 16384; i += 1024) keys[i] = ~0ull;
    __syncthreads();
    for (int s = tid; s < NSLOT; s += 1024){
        float v = act0[s]; int g = 0;
        while (v < 1.0f && v <= Vf && g < 64){
            int pos = atomicAdd(&ctl[2], 1);
            keys[pos] = ((u64)__float_as_uint(v) << 32) | (u32)s;
            v = fminf(1.0f, v + 0.1f); g++;
        }
    }
    __syncthreads();

    for (u32 k2 = 2; k2 <= 16384; k2 <<= 1){
        for (u32 j = k2 >> 1; j > 0; j >>= 1){
            for (u32 i = tid; i < 16384; i += 1024){
                u32 ixj = i ^ j;
                if (ixj > i){
                    u64 a = keys[i], b = keys[ixj];
                    bool up = ((i & k2) == 0);
                    if ((a > b) == up){ keys[i] = b; keys[ixj] = a; }
                }
            }
            __syncthreads();
        }
    }

    for (int r = tid; r < m_count; r += 1024){
        u32 slot = (u32)keys[r] & 0xFFFFu;
        g_pick[ml[r]] = slot | 0x30000u;
    }
#pragma unroll
    for (int j = 0; j < 8; j++)
        if (!(inf8[j] & 0x20000u)) g_pick[base + j] = 0u;
    for (int i = tid; i < NSLOT; i += 1024) cnt[i] = 0;
    __syncthreads();
    for (int r = tid; r < m_count; r += 1024)
        atomicAdd(&cnt[(u32)keys[r] & 0xFFFFu], 1);
    __syncthreads();
    for (int s = tid; s < NSLOT; s += 1024){
        float v = act0[s]; int k = cnt[s];
        for (int j = 0; j < k; j++) v = fminf(1.0f, v + 0.1f);
        g_act[s] = v;
        g_lb[s] = (v < 0.01f) ? -1e30f : logf(v);
    }
    for (int n = tid; n < T_TOK; n += 1024) g_rowsum[n] = 0.f;
}

// ---------------- slow exact scan (fallback, flag-gated) -------------------
__global__ __launch_bounds__(256) void scan_kernel(const float* __restrict__ act0)
{
    if (g_scanflag == 0) return;
    __shared__ __align__(16) float s_act[NSLOT];
    __shared__ __align__(16) float s_gmin[128];
    __shared__ int s_gidx[128];
    int tid = threadIdx.x;
    for (int i = tid; i < NSLOT; i += 256) s_act[i] = act0[i];
    __syncthreads();
    int wid = tid >> 5, lane = tid & 31;
    for (int g = wid; g < 128; g += 8){
        float v = s_act[g * 32 + lane];
        unsigned mv = __reduce_min_sync(FULLM, __float_as_uint(v));
        unsigned bal = __ballot_sync(FULLM, __float_as_uint(v) == mv);
        if (lane == 0){ s_gmin[g] = __uint_as_float(mv); s_gidx[g] = g * 32 + (__ffs(bal) - 1); }
    }
    __syncthreads();
    if (wid == 0){
        unsigned myinfo = 0;
        for (int t = 0; t < T_TOK; t++){
            if ((t & 31) == 0) myinfo = __ldg(&g_info[t + lane]);
            unsigned info = __shfl_sync(FULLM, myinfo, t & 31);
            if (info & 0x20000u){
                int slot;
                if (info & 0x10000u){
                    float4 q4 = *(const float4*)&s_gmin[lane * 4];
                    float bv = q4.x; int bg = lane * 4;
                    if (q4.y < bv){ bv = q4.y; bg = lane * 4 + 1; }
                    if (q4.z < bv){ bv = q4.z; bg = lane * 4 + 2; }
                    if (q4.w < bv){ bv = q4.w; bg = lane * 4 + 3; }
                    unsigned mv = __reduce_min_sync(FULLM, __float_as_uint(bv));
                    unsigned bal = __ballot_sync(FULLM, __float_as_uint(bv) == mv);
                    int L = __ffs(bal) - 1;
                    int grp = __shfl_sync(FULLM, bg, L);
                    slot = s_gidx[grp];
                } else {
                    slot = (int)(info & 0xFFFFu);
                }
                float na = fminf(1.0f, s_act[slot] + 0.1f);
                if (lane == 0) s_act[slot] = na;
                __syncwarp();
                int g = slot >> 5;
                float v = s_act[g * 32 + lane];
                unsigned mv2 = __reduce_min_sync(FULLM, __float_as_uint(v));
                unsigned bal2 = __ballot_sync(FULLM, __float_as_uint(v) == mv2);
                if (lane == 0){
                    s_gmin[g] = __uint_as_float(mv2);
                    s_gidx[g] = g * 32 + (__ffs(bal2) - 1);
                    g_pick[t] = (unsigned)slot | (info & 0x10000u) | 0x20000u;
                }
                __syncwarp();
            } else {
                if (lane == 0) g_pick[t] = 0u;
            }
        }
    }
    __syncthreads();
    for (int i = tid; i < NSLOT; i += 256){
        float v = s_act[i];
        g_act[i] = v;
        g_lb[i] = (v < 0.01f) ? -1e30f : logf(v);
    }
    for (int n = tid; n < T_TOK; n += 256) g_rowsum[n] = 0.f;
}

// ---------------- rebuild: EMA replay + direct fp16 kb split ---------------
__global__ __launch_bounds__(256) void rebuild_kernel(
    const float* __restrict__ keys0, const float* __restrict__ values0)
{
    int wid = threadIdx.x >> 5, lane = threadIdx.x & 31;
    int s = blockIdx.x * 8 + wid;
    float kreg[8], vreg[8];
#pragma unroll
    for (int r = 0; r < 8; r++){
        kreg[r] = keys0[s * DIM + lane + 32 * r];
        vreg[r] = values0[s * DIM + lane + 32 * r];
    }
    for (int base = 0; base < T_TOK; base += 32){
        unsigned pk = __ldg(&g_pick[base + lane]);
        unsigned match = __ballot_sync(FULLM,
            (pk & 0x20000u) && ((pk & 0xFFFFu) == (unsigned)s));
        while (match){
            int bl = __ffs(match) - 1;
            match &= match - 1;
            unsigned pkb = __shfl_sync(FULLM, pk, bl);
            float alpha = (pkb & 0x10000u) ? 0.9f : 0.3f;
            float om = 1.0f - alpha;
            int t = base + bl;
            const float* kr = &g_k[(size_t)t * DIM];
            const float* vr = &g_v[(size_t)t * DIM];
#pragma unroll
            for (int r = 0; r < 8; r++){
                kreg[r] = om * kreg[r] + alpha * __ldg(&kr[lane + 32 * r]);
                vreg[r] = om * vreg[r] + alpha * __ldg(&vr[lane + 32 * r]);
            }
        }
    }
#pragma unroll
    for (int r = 0; r < 8; r++){
        int d0 = s * DIM + lane + 32 * r;
        g_vb[d0] = vreg[r];
        __half hi = __float2half_rn(kreg[r]);
        g_kbh[d0] = hi;
        g_kbl[d0] = __float2half_rn(kreg[r] - __half2float(hi));
    }
}

// --------------------------------- launch --------------------------------
static cudaStream_t s_aux = 0;
static cudaEvent_t s_ev0, s_ev1, s_ev2, s_ev3;
static bool s_init = false;

extern "C" void kernel_launch(void* const* d_in, const int* in_sizes, int n_in,
                              void* d_out, int out_size)
{
    const float* x     = (const float*)d_in[0];
    const void*  wmask = d_in[1];
    const float* keys0 = (const float*)d_in[2];
    const float* vals0 = (const float*)d_in[3];
    const float* act0  = (const float*)d_in[4];
    const float* Wk    = (const float*)d_in[5];
    const float* bk    = (const float*)d_in[6];
    const float* Wv    = (const float*)d_in[7];
    const float* bv    = (const float*)d_in[8];
    const float* Wq    = (const float*)d_in[9];
    const float* bq    = (const float*)d_in[10];
    float* out = (float*)d_out;

    if (!s_init){
        cudaStreamCreateWithFlags(&s_aux, cudaStreamNonBlocking);
        cudaEventCreateWithFlags(&s_ev0, cudaEventDisableTiming);
        cudaEventCreateWithFlags(&s_ev1, cudaEventDisableTiming);
        cudaEventCreateWithFlags(&s_ev2, cudaEventDisableTiming);
        cudaEventCreateWithFlags(&s_ev3, cudaEventDisableTiming);
        cudaFuncSetAttribute(mm_gemm<3,false>, cudaFuncAttributeMaxDynamicSharedMemorySize, SMEMSZ);
        cudaFuncSetAttribute(mm_gemm<1,false>, cudaFuncAttributeMaxDynamicSharedMemorySize, SMEMSZ);
        cudaFuncSetAttribute(mm_gemm<1,true>,  cudaFuncAttributeMaxDynamicSharedMemorySize, SMEMSZ);
        cudaFuncSetAttribute(mm_gemm<2,true>,  cudaFuncAttributeMaxDynamicSharedMemorySize, SMEMSZ);
        cudaFuncSetAttribute(scan_par, cudaFuncAttributeMaxDynamicSharedMemorySize, SP_SMEM);
        s_init = true;
    }

    splitAB_kernel<<<256, 256>>>(x, Wk, Wv, Wq, keys0, bk, bv, bq);
    cudaEventRecord(s_ev0, 0);

    // main stream: proj-k -> simmax -> exact fallback
    mm_gemm<2,true><<<dim3(64,2,1), 256, SMEMSZ>>>(0, 0);      // proj k
    // aux stream: proj v, q
    cudaStreamWaitEvent(s_aux, s_ev0, 0);
    mm_gemm<2,true><<<dim3(64,2,2), 256, SMEMSZ, s_aux>>>(0, 1);
    cudaEventRecord(s_ev1, s_aux);

    mm_gemm<1,false><<<dim3(64,32), 256, SMEMSZ>>>(3, 0);      // simmax + guard
    mm_gemm<3,false><<<dim3(64,32), 256, SMEMSZ>>>(6, 0);      // exact simmax (gated)

    scan_par<<<1, 1024, SP_SMEM>>>(act0, wmask);
    scan_kernel<<<1, 256>>>(act0);
    cudaStreamWaitEvent(0, s_ev1, 0);                          // need g_v, g_qh
    rebuild_kernel<<<NSLOT/8, 256>>>(keys0, vals0);
    cudaEventRecord(s_ev2, 0);

    // aux: vb transpose concurrent with attnA
    cudaStreamWaitEvent(s_aux, s_ev2, 0);
    tsplit_vb<<<dim3(128,8), dim3(32,8), 0, s_aux>>>();
    cudaEventRecord(s_ev3, s_aux);

    mm_gemm<1,true><<<dim3(64,32), 256, SMEMSZ>>>(4, 0);       // attnA
    cudaStreamWaitEvent(0, s_ev3, 0);
    mm_gemm<1,true><<<dim3(64,2,2), 256, SMEMSZ>>>(5, 0);      // attnC splitK=2
    attnC_red<<<T_TOK*DIM/1024, 256>>>(out);
}